// round 2
// baseline (speedup 1.0000x reference)
#include <cuda_runtime.h>
#include <cuda_bf16.h>
#include <cstdint>

// out[m,u] = ||x_m||^2 - 2*(x_m . w_u) + ||w_u||^2
// M = 524288 rows, D = 64, U = 64.
// Cross term via bf16 mma.sync m16n8k16. x2 fp32 (exact from loaded values),
// w2 fp32. w pre-packed into B-fragment order in smem (LDS.64 reads).
// x staged per-warp in swizzled smem bf16, A-frags via ldmatrix.x4.

#define DEPTH 64
#define UNITS 64

__device__ __forceinline__ uint32_t pack_bf16x2(float lo, float hi) {
    // cvt.rn.bf16x2.f32 d, a, b : a -> high half, b -> low half
    uint32_t r;
    asm("cvt.rn.bf16x2.f32 %0, %1, %2;" : "=r"(r) : "f"(hi), "f"(lo));
    return r;
}

__device__ __forceinline__ void mma_bf16(float c[4],
                                         uint32_t a0, uint32_t a1, uint32_t a2, uint32_t a3,
                                         uint32_t b0, uint32_t b1) {
    asm volatile(
        "mma.sync.aligned.m16n8k16.row.col.f32.bf16.bf16.f32 "
        "{%0,%1,%2,%3}, {%4,%5,%6,%7}, {%8,%9}, {%0,%1,%2,%3};"
        : "+f"(c[0]), "+f"(c[1]), "+f"(c[2]), "+f"(c[3])
        : "r"(a0), "r"(a1), "r"(a2), "r"(a3), "r"(b0), "r"(b1));
}

__device__ __forceinline__ void ldsm_x4(uint32_t r[4], uint32_t smem_addr) {
    asm volatile("ldmatrix.sync.aligned.m8n8.x4.shared.b16 {%0,%1,%2,%3}, [%4];"
                 : "=r"(r[0]), "=r"(r[1]), "=r"(r[2]), "=r"(r[3])
                 : "r"(smem_addr));
}

__device__ __forceinline__ uint32_t smem_u32(const void* p) {
    return (uint32_t)__cvta_generic_to_shared(p);
}

__global__ __launch_bounds__(256, 3) void sqdist_kernel(
    const float* __restrict__ x, const float* __restrict__ w,
    float* __restrict__ out)
{
    // w B-fragments: [nt*4 + kb][lane] -> (b0,b1). 8 KB.
    __shared__ uint2 fragB[32][32];
    __shared__ float w2_s[UNITS];
    // per-warp x tile: 16 rows x 128 bytes (64 bf16), swizzled. 16 KB.
    __shared__ __align__(16) char xs[8][16 * 128];
    __shared__ float x2_s[8][16];

    const int tid  = threadIdx.x;
    const int warp = tid >> 5;
    const int lane = tid & 31;

    // ---- w2 (fp32): thread t handles unit n = t/4, d-slice (t%4)*16..+15
    {
        const int n  = tid >> 2;
        const int dq = (tid & 3) * 16;
        const float* wp = w + n * DEPTH + dq;
        float psum = 0.f;
        #pragma unroll
        for (int i = 0; i < 4; i++) {
            float4 v = reinterpret_cast<const float4*>(wp)[i];
            psum += v.x * v.x + v.y * v.y + v.z * v.z + v.w * v.w;
        }
        psum += __shfl_xor_sync(0xffffffffu, psum, 1);
        psum += __shfl_xor_sync(0xffffffffu, psum, 2);
        if ((tid & 3) == 0) w2_s[n] = psum;
    }

    // ---- Pack w into B-fragment order (1024 uint2 entries, 4 per thread).
    #pragma unroll
    for (int e = tid; e < 1024; e += 256) {
        const int l    = e & 31;
        const int kbnt = e >> 5;          // kb = kbnt&3, nt = kbnt>>2
        const int kb   = kbnt & 3;
        const int nt   = kbnt >> 2;
        const int n    = nt * 8 + (l >> 2);
        const int k    = kb * 16 + (l & 3) * 2;
        float2 lo = *reinterpret_cast<const float2*>(w + n * DEPTH + k);
        float2 hi = *reinterpret_cast<const float2*>(w + n * DEPTH + k + 8);
        uint2 f;
        f.x = pack_bf16x2(lo.x, lo.y);
        f.y = pack_bf16x2(hi.x, hi.y);
        fragB[kbnt][l] = f;
    }
    __syncthreads();

    // ---- Load x tile (16 rows per warp), compute x2, convert -> swizzled smem.
    const long row0 = (long)blockIdx.x * 128 + warp * 16;
    {
        const int row_l = lane >> 1;           // 0..15
        const int half  = lane & 1;            // 0 or 1 (cols 0-31 / 32-63)
        const float4* xp4 = reinterpret_cast<const float4*>(
            x + (row0 + row_l) * DEPTH + half * 32);
        float4 v[8];
        #pragma unroll
        for (int i = 0; i < 8; i++) v[i] = xp4[i];

        float s = 0.f;
        #pragma unroll
        for (int i = 0; i < 8; i++)
            s += v[i].x * v[i].x + v[i].y * v[i].y + v[i].z * v[i].z + v[i].w * v[i].w;
        s += __shfl_xor_sync(0xffffffffu, s, 1);
        if (half == 0) x2_s[warp][row_l] = s;

        char* base = xs[warp] + row_l * 128;
        #pragma unroll
        for (int c = 0; c < 4; c++) {
            uint4 chunk;
            chunk.x = pack_bf16x2(v[2*c].x,   v[2*c].y);
            chunk.y = pack_bf16x2(v[2*c].z,   v[2*c].w);
            chunk.z = pack_bf16x2(v[2*c+1].x, v[2*c+1].y);
            chunk.w = pack_bf16x2(v[2*c+1].z, v[2*c+1].w);
            const int ch   = half * 4 + c;            // logical 16B chunk 0..7
            const int phys = ch ^ (row_l & 7);        // swizzle
            *reinterpret_cast<uint4*>(base + phys * 16) = chunk;
        }
    }
    __syncwarp();

    // ---- A fragments via ldmatrix.x4 (one per kb).
    uint32_t ab[4][4];
    {
        const int row   = (lane & 7) + ((lane >> 3) & 1) * 8;
        const int chsel = (lane >> 4);                 // 0: k 0-7, 1: k 8-15
        const uint32_t base = smem_u32(xs[warp] + row * 128);
        #pragma unroll
        for (int kb = 0; kb < 4; kb++) {
            const int phys = (2 * kb + chsel) ^ (row & 7);
            ldsm_x4(ab[kb], base + phys * 16);
        }
    }

    // ---- GEMM: 8 n-tiles x 4 k-blocks.
    const int g  = lane >> 2;
    const int t4 = lane & 3;
    float acc[8][4];
    #pragma unroll
    for (int nt = 0; nt < 8; nt++) {
        acc[nt][0] = acc[nt][1] = acc[nt][2] = acc[nt][3] = 0.f;
        #pragma unroll
        for (int kb = 0; kb < 4; kb++) {
            uint2 b = fragB[nt * 4 + kb][lane];
            mma_bf16(acc[nt], ab[kb][0], ab[kb][1], ab[kb][2], ab[kb][3], b.x, b.y);
        }
    }

    // ---- Epilogue: out = x2 + w2 - 2*acc.
    const float p_lo = x2_s[warp][g];
    const float p_hi = x2_s[warp][g + 8];
    #pragma unroll
    for (int nt = 0; nt < 8; nt++) {
        const int ucol = nt * 8 + t4 * 2;
        float2 w2v = *reinterpret_cast<const float2*>(&w2_s[ucol]);
        float2 o0, o1;
        o0.x = p_lo + w2v.x - 2.f * acc[nt][0];
        o0.y = p_lo + w2v.y - 2.f * acc[nt][1];
        o1.x = p_hi + w2v.x - 2.f * acc[nt][2];
        o1.y = p_hi + w2v.y - 2.f * acc[nt][3];
        *reinterpret_cast<float2*>(out + (row0 + g) * UNITS + ucol)     = o0;
        *reinterpret_cast<float2*>(out + (row0 + g + 8) * UNITS + ucol) = o1;
    }
}

extern "C" void kernel_launch(void* const* d_in, const int* in_sizes, int n_in,
                              void* d_out, int out_size) {
    const float* x = (const float*)d_in[0];
    const float* w = (const float*)d_in[1];
    float* out = (float*)d_out;
    const int M = in_sizes[0] / DEPTH;   // 524288
    const int grid = M / 128;            // 4096
    sqdist_kernel<<<grid, 256>>>(x, w, out);
}

// round 3
// speedup vs baseline: 1.3582x; 1.3582x over previous
#include <cuda_runtime.h>
#include <cuda_bf16.h>
#include <cstdint>

// out[m,u] = ||x_m||^2 - 2*(x_m . w_u) + ||w_u||^2
// M = 524288, D = 64, U = 64. Cross term via bf16 mma.sync m16n8k16.
// A-frags loaded directly global->reg (R1 scheme). B pre-packed in smem
// fragment order (LDS.64). Output staged via swizzled smem -> STG.128.

#define DEPTH 64
#define UNITS 64

__device__ __forceinline__ uint32_t pack_bf16x2(float lo, float hi) {
    // cvt.rn.bf16x2.f32 d, a, b : a -> high half, b -> low half
    uint32_t r;
    asm("cvt.rn.bf16x2.f32 %0, %1, %2;" : "=r"(r) : "f"(hi), "f"(lo));
    return r;
}

__device__ __forceinline__ void mma_bf16(float c[4],
                                         uint32_t a0, uint32_t a1, uint32_t a2, uint32_t a3,
                                         uint32_t b0, uint32_t b1) {
    asm volatile(
        "mma.sync.aligned.m16n8k16.row.col.f32.bf16.bf16.f32 "
        "{%0,%1,%2,%3}, {%4,%5,%6,%7}, {%8,%9}, {%0,%1,%2,%3};"
        : "+f"(c[0]), "+f"(c[1]), "+f"(c[2]), "+f"(c[3])
        : "r"(a0), "r"(a1), "r"(a2), "r"(a3), "r"(b0), "r"(b1));
}

__global__ __launch_bounds__(256, 3) void sqdist_kernel(
    const float* __restrict__ x, const float* __restrict__ w,
    float* __restrict__ out)
{
    // w B-fragments: [nt*4 + kb][lane] -> (b0,b1). 8 KB.
    __shared__ uint2 fragB[32][32];
    __shared__ float w2_s[UNITS];
    // per-warp output stage: 8 rows x 32 float2 slots (swizzled). 16 KB.
    __shared__ __align__(16) float2 stage2[8][8 * 32];

    const int tid  = threadIdx.x;
    const int warp = tid >> 5;
    const int lane = tid & 31;

    // ---- w2 (fp32): thread t handles unit n = t/4, d-slice (t%4)*16..+15
    {
        const int n  = tid >> 2;
        const int dq = (tid & 3) * 16;
        const float* wp = w + n * DEPTH + dq;
        float psum = 0.f;
        #pragma unroll
        for (int i = 0; i < 4; i++) {
            float4 v = reinterpret_cast<const float4*>(wp)[i];
            psum += v.x * v.x + v.y * v.y + v.z * v.z + v.w * v.w;
        }
        psum += __shfl_xor_sync(0xffffffffu, psum, 1);
        psum += __shfl_xor_sync(0xffffffffu, psum, 2);
        if ((tid & 3) == 0) w2_s[n] = psum;
    }

    // ---- Pack w into B-fragment order (1024 uint2 entries, 4 per thread).
    #pragma unroll
    for (int e = tid; e < 1024; e += 256) {
        const int l    = e & 31;
        const int kbnt = e >> 5;          // kb = kbnt&3, nt = kbnt>>2
        const int kb   = kbnt & 3;
        const int nt   = kbnt >> 2;
        const int n    = nt * 8 + (l >> 2);
        const int k    = kb * 16 + (l & 3) * 2;
        float2 lo = *reinterpret_cast<const float2*>(w + n * DEPTH + k);
        float2 hi = *reinterpret_cast<const float2*>(w + n * DEPTH + k + 8);
        uint2 f;
        f.x = pack_bf16x2(lo.x, lo.y);
        f.y = pack_bf16x2(hi.x, hi.y);
        fragB[kbnt][l] = f;
    }
    __syncthreads();

    const int g  = lane >> 2;   // 0..7
    const int t4 = lane & 3;    // 0..3

    const long row0 = (long)blockIdx.x * 128 + warp * 16;
    const float* xp = x + row0 * DEPTH;

    // ---- Load A fragments (fp32) directly from global.
    // reg r: row = g + (r&1)*8, col = kb*16 + t4*2 + (r>>1)*8
    float2 af[4][4];
    #pragma unroll
    for (int kb = 0; kb < 4; kb++) {
        const int kbase = kb * 16 + t4 * 2;
        #pragma unroll
        for (int r = 0; r < 4; r++) {
            const int row = g + (r & 1) * 8;
            const int col = kbase + (r >> 1) * 8;
            af[kb][r] = *reinterpret_cast<const float2*>(xp + row * DEPTH + col);
        }
    }

    // ---- x2 partial sums (exact fp32), reduce within lane-quad.
    float p_lo = 0.f, p_hi = 0.f;
    #pragma unroll
    for (int kb = 0; kb < 4; kb++) {
        p_lo += af[kb][0].x * af[kb][0].x + af[kb][0].y * af[kb][0].y;
        p_lo += af[kb][2].x * af[kb][2].x + af[kb][2].y * af[kb][2].y;
        p_hi += af[kb][1].x * af[kb][1].x + af[kb][1].y * af[kb][1].y;
        p_hi += af[kb][3].x * af[kb][3].x + af[kb][3].y * af[kb][3].y;
    }
    p_lo += __shfl_xor_sync(0xffffffffu, p_lo, 1);
    p_lo += __shfl_xor_sync(0xffffffffu, p_lo, 2);
    p_hi += __shfl_xor_sync(0xffffffffu, p_hi, 1);
    p_hi += __shfl_xor_sync(0xffffffffu, p_hi, 2);

    // ---- Convert A to bf16x2 fragments.
    uint32_t ab[4][4];
    #pragma unroll
    for (int kb = 0; kb < 4; kb++)
        #pragma unroll
        for (int r = 0; r < 4; r++)
            ab[kb][r] = pack_bf16x2(af[kb][r].x, af[kb][r].y);

    // ---- GEMM: 8 n-tiles x 4 k-blocks.
    float acc[8][4];
    #pragma unroll
    for (int nt = 0; nt < 8; nt++) {
        acc[nt][0] = acc[nt][1] = acc[nt][2] = acc[nt][3] = 0.f;
        #pragma unroll
        for (int kb = 0; kb < 4; kb++) {
            uint2 b = fragB[nt * 4 + kb][lane];
            mma_bf16(acc[nt], ab[kb][0], ab[kb][1], ab[kb][2], ab[kb][3], b.x, b.y);
        }
    }

    // ---- Epilogue: out = x2 + w2 - 2*acc.
    // Two passes: rows 0-7 (acc[.,0..1], p_lo) then rows 8-15 (acc[.,2..3], p_hi).
    // Stage layout: slot = g*32 + ((nt*4 + t4) ^ ((g&3)*4))  (conflict-free).
    const int jj   = lane & 15;          // 0..15 (float4 segment within row)
    const int rhal = lane >> 4;          // 0..1
    #pragma unroll
    for (int pass = 0; pass < 2; pass++) {
        const float p = pass ? p_hi : p_lo;
        #pragma unroll
        for (int nt = 0; nt < 8; nt++) {
            const int ucol = nt * 8 + t4 * 2;
            float2 w2v = *reinterpret_cast<const float2*>(&w2_s[ucol]);
            float2 o;
            o.x = p + w2v.x - 2.f * acc[nt][2 * pass];
            o.y = p + w2v.y - 2.f * acc[nt][2 * pass + 1];
            const int s = nt * 4 + t4;
            stage2[warp][g * 32 + (s ^ ((g & 3) * 4))] = o;
        }
        __syncwarp();
        // Coalesced writeback: 4 x STG.128 per pass per lane.
        #pragma unroll
        for (int s8 = 0; s8 < 4; s8++) {
            const int r = s8 * 2 + rhal;             // local row 0..7
            const int phys = (2 * jj) ^ ((r & 3) * 4);
            float4 v = *reinterpret_cast<const float4*>(&stage2[warp][r * 32 + phys]);
            const long grow = row0 + pass * 8 + r;
            *reinterpret_cast<float4*>(out + grow * UNITS + jj * 4) = v;
        }
        __syncwarp();
    }
}

extern "C" void kernel_launch(void* const* d_in, const int* in_sizes, int n_in,
                              void* d_out, int out_size) {
    const float* x = (const float*)d_in[0];
    const float* w = (const float*)d_in[1];
    float* out = (float*)d_out;
    const int M = in_sizes[0] / DEPTH;   // 524288
    const int grid = M / 128;            // 4096
    sqdist_kernel<<<grid, 256>>>(x, w, out);
}